// round 4
// baseline (speedup 1.0000x reference)
#include <cuda_runtime.h>
#include <cuda_bf16.h>
#include <cstdint>

#define B_   64
#define NN_  64
#define HL_  50
#define IN_  384
#define POS_ 64
#define ATT_ 256
#define NEWS_ 448
#define W1COLS_ 896

// Scratch
__device__ float g_pn[B_ * NN_ * ATT_];
__device__ float g_pl[B_ * HL_ * ATT_];
__device__ float g_cn[ATT_];
__device__ float g_cl[HL_ * ATT_];

__device__ __forceinline__ float tanh_fast(float x) {
    float y; asm("tanh.approx.f32 %0, %1;" : "=f"(y) : "f"(x)); return y;
}
__device__ __forceinline__ uint32_t to_tf32(float f) {
    uint32_t r; asm("cvt.rna.tf32.f32 %0, %1;" : "=r"(r) : "f"(f)); return r;
}
__device__ __forceinline__ void mma_tf32(float* c, const uint32_t* a, const uint32_t* b) {
    asm volatile(
        "mma.sync.aligned.m16n8k8.row.col.f32.tf32.tf32.f32 "
        "{%0,%1,%2,%3}, {%4,%5,%6,%7}, {%8,%9}, {%0,%1,%2,%3};"
        : "+f"(c[0]), "+f"(c[1]), "+f"(c[2]), "+f"(c[3])
        : "r"(a[0]), "r"(a[1]), "r"(a[2]), "r"(a[3]), "r"(b[0]), "r"(b[1]));
}

// ---------------------------------------------------------------------------
// Kernel 1: build nf -> out second half
// ---------------------------------------------------------------------------
__global__ __launch_bounds__(256) void setup_kernel(
    const float* __restrict__ news_vec,
    const float* __restrict__ pos_emb,
    float* __restrict__ nf_out)
{
    const int NF_TOTAL = B_ * NN_ * NEWS_;
    int idx = blockIdx.x * 256 + threadIdx.x;
    if (idx < NF_TOTAL) {
        int d = idx % NEWS_;
        int r = idx / NEWS_;
        nf_out[idx] = (d < IN_) ? news_vec[r * IN_ + d] : pos_emb[d - IN_];
    }
}

// ---------------------------------------------------------------------------
// Kernel 2: cn / cl bias folding (exact fp32)
// ---------------------------------------------------------------------------
__global__ __launch_bounds__(256) void cncl_kernel(
    const float* __restrict__ pos_emb,
    const float* __restrict__ W1,
    const float* __restrict__ b1)
{
    int a = threadIdx.x;
    int blk = blockIdx.x;
    if (blk == 0) {
        float s = b1[a];
        const float* w = W1 + a * W1COLS_ + IN_;
        #pragma unroll 8
        for (int p = 0; p < POS_; p++) s += pos_emb[p] * w[p];
        g_cn[a] = s;
    } else {
        int h = blk - 1;
        float s = 0.f;
        const float* w  = W1 + a * W1COLS_ + NEWS_ + IN_;
        const float* pe = pos_emb + (1 + h) * POS_;
        #pragma unroll 8
        for (int p = 0; p < POS_; p++) s += pe[p] * w[p];
        g_cl[h * ATT_ + a] = s;
    }
}

// ---------------------------------------------------------------------------
// Kernel 3: mma.sync tf32 GEMM (unchanged from R3)
// ---------------------------------------------------------------------------
#define BK 32
#define LDT 36
#define NKT (IN_ / BK)

__global__ __launch_bounds__(256) void gemm_mma_kernel(
    const float* __restrict__ news_vec,
    const float* __restrict__ log_vec,
    const float* __restrict__ W1)
{
    __shared__ uint32_t As[128 * LDT];
    __shared__ uint32_t Ws[128 * LDT];

    int tid  = threadIdx.x;
    int wid  = tid >> 5, lane = tid & 31;
    int gid  = lane >> 2, tig = lane & 3;
    int wm   = wid & 1;
    int wn   = wid >> 1;

    int bx   = blockIdx.x;
    int nh   = bx & 1;
    int tile = bx >> 1;
    int mode, mtile, w_off;
    const float* A;
    if (tile < 32) { mode = 0; mtile = tile;      A = news_vec; w_off = 0; }
    else           { mode = 1; mtile = tile - 32; A = log_vec;  w_off = NEWS_; }
    int n_base = nh * 128;

    int lrow = tid >> 3;
    int lf4  = tid & 7;
    const float* Abase = A  + (size_t)(mtile * 128 + lrow) * IN_ + lf4 * 4;
    const float* Wbase = W1 + (size_t)(n_base + lrow) * W1COLS_ + w_off + lf4 * 4;

    float acc[4][4][4];
    #pragma unroll
    for (int i = 0; i < 4; i++)
        #pragma unroll
        for (int j = 0; j < 4; j++)
            #pragma unroll
            for (int k = 0; k < 4; k++) acc[i][j][k] = 0.f;

    float4 aReg[4], wReg[4];
    #pragma unroll
    for (int p = 0; p < 4; p++) {
        aReg[p] = *(const float4*)(Abase + (size_t)p * 32 * IN_);
        wReg[p] = *(const float4*)(Wbase + (size_t)p * 32 * W1COLS_);
    }

    for (int kt = 0; kt < NKT; kt++) {
        #pragma unroll
        for (int p = 0; p < 4; p++) {
            uint32_t* as = &As[(p * 32 + lrow) * LDT + lf4 * 4];
            as[0] = to_tf32(aReg[p].x); as[1] = to_tf32(aReg[p].y);
            as[2] = to_tf32(aReg[p].z); as[3] = to_tf32(aReg[p].w);
            uint32_t* ws = &Ws[(p * 32 + lrow) * LDT + lf4 * 4];
            ws[0] = to_tf32(wReg[p].x); ws[1] = to_tf32(wReg[p].y);
            ws[2] = to_tf32(wReg[p].z); ws[3] = to_tf32(wReg[p].w);
        }
        __syncthreads();

        if (kt + 1 < NKT) {
            const float* An = Abase + (kt + 1) * BK;
            const float* Wn = Wbase + (kt + 1) * BK;
            #pragma unroll
            for (int p = 0; p < 4; p++) {
                aReg[p] = *(const float4*)(An + (size_t)p * 32 * IN_);
                wReg[p] = *(const float4*)(Wn + (size_t)p * 32 * W1COLS_);
            }
        }

        #pragma unroll
        for (int kk = 0; kk < BK; kk += 8) {
            uint32_t afr[4][4], bfr[4][2];
            #pragma unroll
            for (int mf = 0; mf < 4; mf++) {
                int r0 = (wm * 64 + mf * 16 + gid) * LDT + kk + tig;
                afr[mf][0] = As[r0];
                afr[mf][1] = As[r0 + 8 * LDT];
                afr[mf][2] = As[r0 + 4];
                afr[mf][3] = As[r0 + 8 * LDT + 4];
            }
            #pragma unroll
            for (int nf = 0; nf < 4; nf++) {
                int c0 = (wn * 32 + nf * 8 + gid) * LDT + kk + tig;
                bfr[nf][0] = Ws[c0];
                bfr[nf][1] = Ws[c0 + 4];
            }
            #pragma unroll
            for (int mf = 0; mf < 4; mf++)
                #pragma unroll
                for (int nf = 0; nf < 4; nf++)
                    mma_tf32(acc[mf][nf], afr[mf], bfr[nf]);
        }
        __syncthreads();
    }

    float* outp = (mode == 0) ? g_pn : g_pl;
    #pragma unroll
    for (int mf = 0; mf < 4; mf++) {
        int r0 = mtile * 128 + wm * 64 + mf * 16 + gid;
        int r1 = r0 + 8;
        const float* bias0;
        const float* bias1;
        if (mode == 0) { bias0 = g_cn; bias1 = g_cn; }
        else { bias0 = g_cl + (r0 % HL_) * ATT_; bias1 = g_cl + (r1 % HL_) * ATT_; }
        #pragma unroll
        for (int nf = 0; nf < 4; nf++) {
            int c = n_base + wn * 32 + nf * 8 + 2 * tig;
            float2 v0, v1;
            v0.x = acc[mf][nf][0] + bias0[c];
            v0.y = acc[mf][nf][1] + bias0[c + 1];
            v1.x = acc[mf][nf][2] + bias1[c];
            v1.y = acc[mf][nf][3] + bias1[c + 1];
            *(float2*)(outp + (size_t)r0 * ATT_ + c) = v0;
            *(float2*)(outp + (size_t)r1 * ATT_ + c) = v1;
        }
    }
}

// ---------------------------------------------------------------------------
// Kernel 4: warp-independent fused core with mask elision.
// Block = (b, half). Stage compact pl/lf for ACTIVE h only, then each of
// 16 warps processes 2 n's end-to-end with no block barriers.
// ---------------------------------------------------------------------------
// smem layout (floats unless noted):
//   pl_s   [50 * 256]              offset 0
//   lf_s   [50 * 448]              offset 12800
//   lg     [16 * 52]               offset 35200   (per-warp logits/attn)
//   act    [52] (int)              offset 36032
//   meta   [2]  (int: cnt, unif)   offset 36084
#define CORE_SMEM_FLOATS (36096)
#define CORE_SMEM (CORE_SMEM_FLOATS * 4)

__global__ __launch_bounds__(512, 1) void core_kernel(
    const float* __restrict__ log_vec,
    const float* __restrict__ pos_emb,
    const int*   __restrict__ log_mask,
    const float* __restrict__ W2,
    const float* __restrict__ b2,
    float* __restrict__ out)
{
    extern __shared__ float sm[];
    float* pl_s = sm;
    float* lf_s = sm + 12800;
    float* lg   = sm + 35200;
    int*   act  = (int*)(sm + 36032);
    int*   meta = (int*)(sm + 36084);

    int tid  = threadIdx.x;
    int b    = blockIdx.x >> 1;
    int half = blockIdx.x & 1;
    int warp = tid >> 5, lane = tid & 31;

    // --- phase 0: active-h list ---
    if (tid == 0) {
        int c = 0;
        #pragma unroll
        for (int h = 0; h < HL_; h++)
            if (log_mask[b * HL_ + h] != 0) act[c++] = h;
        int unif = (c == 0);
        if (unif) { for (int h = 0; h < HL_; h++) act[h] = h; c = HL_; }
        meta[0] = c;
        meta[1] = unif;
    }
    __syncthreads();
    int cnt  = meta[0];
    int unif = meta[1];

    // --- phase 1: stage compact pl (cnt x 256) and lf (cnt x 448) ---
    {
        int npl = cnt * 64;                    // float4 count
        const float4* plg = (const float4*)(g_pl + (size_t)b * HL_ * ATT_);
        for (int i = tid; i < npl; i += 512) {
            int j = i >> 6, r = i & 63;
            ((float4*)pl_s)[(size_t)j * 64 + r] = plg[(size_t)act[j] * 64 + r];
        }
        int nlf = cnt * 112;                   // 96 from log_vec + 16 from pos
        for (int i = tid; i < nlf; i += 512) {
            int j = i / 112, r = i % 112;
            int h = act[j];
            float4 v;
            if (r < 96)
                v = *(const float4*)(log_vec + ((size_t)(b * HL_ + h) * IN_) + r * 4);
            else
                v = *(const float4*)(pos_emb + (size_t)(1 + h) * POS_ + (r - 96) * 4);
            *(float4*)(lf_s + (size_t)j * NEWS_ + r * 4) = v;
        }
    }

    // per-lane W2 slice
    float w2r[8];
    #pragma unroll
    for (int k = 0; k < 8; k++) w2r[k] = W2[lane + 32 * k];
    float bias2 = b2[0];
    __syncthreads();

    // --- phase 2: each warp owns 2 n's, no more block barriers ---
    float* mylg = lg + warp * 52;

    for (int t = 0; t < 2; t++) {
        int n  = half * 32 + t * 16 + warp;
        int bn = b * NN_ + n;

        // pn into registers
        float pnr[8];
        #pragma unroll
        for (int k = 0; k < 8; k++) pnr[k] = g_pn[(size_t)bn * ATT_ + lane + 32 * k];

        if (!unif) {
            // logits for active h
            for (int j = 0; j < cnt; j++) {
                const float* plrow = pl_s + (size_t)j * ATT_;
                float s = 0.f;
                #pragma unroll
                for (int k = 0; k < 8; k++)
                    s += tanh_fast(pnr[k] + plrow[lane + 32 * k]) * w2r[k];
                #pragma unroll
                for (int o = 16; o > 0; o >>= 1)
                    s += __shfl_xor_sync(0xffffffffu, s, o);
                if (lane == 0) mylg[j] = s + bias2;
            }
            __syncwarp();
            // warp softmax over cnt values
            float v0 = (lane < cnt)      ? mylg[lane]      : -3.0e38f;
            float v1 = (lane + 32 < cnt) ? mylg[lane + 32] : -3.0e38f;
            float mx = fmaxf(v0, v1);
            #pragma unroll
            for (int o = 16; o > 0; o >>= 1)
                mx = fmaxf(mx, __shfl_xor_sync(0xffffffffu, mx, o));
            float e0 = __expf(v0 - mx), e1 = __expf(v1 - mx);
            float smv = e0 + e1;
            #pragma unroll
            for (int o = 16; o > 0; o >>= 1)
                smv += __shfl_xor_sync(0xffffffffu, smv, o);
            float inv = 1.f / smv;
            if (lane < cnt)      mylg[lane]      = e0 * inv;
            if (lane + 32 < cnt) mylg[lane + 32] = e1 * inv;
            __syncwarp();
        } else {
            if (lane < cnt)      mylg[lane]      = 1.f / HL_;
            if (lane + 32 < cnt) mylg[lane + 32] = 1.f / HL_;
            __syncwarp();
        }

        // epilogue: out[bn,d] = sum_j attn[j] * lf_s[j,d]
        #pragma unroll 2
        for (int c = 0; c < 14; c++) {
            int d = c * 32 + lane;
            float acc = 0.f;
            int j = 0;
            for (; j + 2 <= cnt; j += 2) {
                acc += mylg[j]     * lf_s[(size_t)j * NEWS_ + d];
                acc += mylg[j + 1] * lf_s[(size_t)(j + 1) * NEWS_ + d];
            }
            if (j < cnt) acc += mylg[j] * lf_s[(size_t)j * NEWS_ + d];
            out[(size_t)bn * NEWS_ + d] = acc;
        }
    }
}

// ---------------------------------------------------------------------------
extern "C" void kernel_launch(void* const* d_in, const int* in_sizes, int n_in,
                              void* d_out, int out_size)
{
    const float* log_vec  = (const float*)d_in[0];
    const int*   log_mask = (const int*)  d_in[1];
    const float* news_vec = (const float*)d_in[2];
    const float* pos_emb  = (const float*)d_in[3];
    const float* W1       = (const float*)d_in[4];
    const float* b1       = (const float*)d_in[5];
    const float* W2       = (const float*)d_in[6];
    const float* b2       = (const float*)d_in[7];
    float* out = (float*)d_out;

    const int NF_TOTAL = B_ * NN_ * NEWS_;
    cudaFuncSetAttribute(core_kernel, cudaFuncAttributeMaxDynamicSharedMemorySize, CORE_SMEM);

    setup_kernel<<<(NF_TOTAL + 255) / 256, 256>>>(news_vec, pos_emb, out + NF_TOTAL);
    cncl_kernel<<<HL_ + 1, 256>>>(pos_emb, W1, b1);
    gemm_mma_kernel<<<114, 256>>>(news_vec, log_vec, W1);
    core_kernel<<<B_ * 2, 512, CORE_SMEM>>>(log_vec, pos_emb, log_mask, W2, b2, out);
}

// round 5
// speedup vs baseline: 1.3395x; 1.3395x over previous
#include <cuda_runtime.h>
#include <cuda_bf16.h>
#include <cstdint>

#define B_   64
#define NN_  64
#define HL_  50
#define IN_  384
#define POS_ 64
#define ATT_ 256
#define NEWS_ 448
#define W1COLS_ 896

// Scratch
__device__ float g_pn[B_ * NN_ * ATT_];
__device__ float g_pl[B_ * HL_ * ATT_];
__device__ float g_cn[ATT_];
__device__ float g_cl[HL_ * ATT_];
__device__ float g_attn[B_ * NN_ * 52];
__device__ int   g_act[B_ * 52];
__device__ int   g_cntflag[B_];          // cnt | (unif<<8)

__device__ __forceinline__ float tanh_fast(float x) {
    float y; asm("tanh.approx.f32 %0, %1;" : "=f"(y) : "f"(x)); return y;
}
__device__ __forceinline__ uint32_t to_tf32(float f) {
    uint32_t r; asm("cvt.rna.tf32.f32 %0, %1;" : "=r"(r) : "f"(f)); return r;
}
__device__ __forceinline__ void mma_tf32(float* c, const uint32_t* a, const uint32_t* b) {
    asm volatile(
        "mma.sync.aligned.m16n8k8.row.col.f32.tf32.tf32.f32 "
        "{%0,%1,%2,%3}, {%4,%5,%6,%7}, {%8,%9}, {%0,%1,%2,%3};"
        : "+f"(c[0]), "+f"(c[1]), "+f"(c[2]), "+f"(c[3])
        : "r"(a[0]), "r"(a[1]), "r"(a[2]), "r"(a[3]), "r"(b[0]), "r"(b[1]));
}

// ---------------------------------------------------------------------------
// Kernel 1: build nf -> out second half
// ---------------------------------------------------------------------------
__global__ __launch_bounds__(256) void setup_kernel(
    const float* __restrict__ news_vec,
    const float* __restrict__ pos_emb,
    float* __restrict__ nf_out)
{
    const int NF_TOTAL = B_ * NN_ * NEWS_;
    int idx = blockIdx.x * 256 + threadIdx.x;
    if (idx < NF_TOTAL) {
        int d = idx % NEWS_;
        int r = idx / NEWS_;
        nf_out[idx] = (d < IN_) ? news_vec[r * IN_ + d] : pos_emb[d - IN_];
    }
}

// ---------------------------------------------------------------------------
// Kernel 2: cn / cl bias folding + per-b mask compaction
// ---------------------------------------------------------------------------
__global__ __launch_bounds__(256) void cncl_kernel(
    const float* __restrict__ pos_emb,
    const float* __restrict__ W1,
    const float* __restrict__ b1,
    const int*   __restrict__ log_mask)
{
    int a = threadIdx.x;
    int blk = blockIdx.x;
    if (blk == 0) {
        float s = b1[a];
        const float* w = W1 + a * W1COLS_ + IN_;
        #pragma unroll 8
        for (int p = 0; p < POS_; p++) s += pos_emb[p] * w[p];
        g_cn[a] = s;
    } else if (blk <= HL_) {
        int h = blk - 1;
        float s = 0.f;
        const float* w  = W1 + a * W1COLS_ + NEWS_ + IN_;
        const float* pe = pos_emb + (1 + h) * POS_;
        #pragma unroll 8
        for (int p = 0; p < POS_; p++) s += pe[p] * w[p];
        g_cl[h * ATT_ + a] = s;
    } else {
        // mask compaction: thread t handles b = t (256 threads, 64 b's)
        int b = a;
        if (b < B_) {
            int c = 0;
            int buf[HL_];
            #pragma unroll
            for (int h = 0; h < HL_; h++)
                if (log_mask[b * HL_ + h] != 0) buf[c++] = h;
            int unif = (c == 0);
            if (unif) { for (int h = 0; h < HL_; h++) buf[h] = h; c = HL_; }
            for (int j = 0; j < c; j++) g_act[b * 52 + j] = buf[j];
            g_cntflag[b] = c | (unif << 8);
        }
    }
}

// ---------------------------------------------------------------------------
// Kernel 3: mma.sync tf32 GEMM (unchanged)
// ---------------------------------------------------------------------------
#define BK 32
#define LDT 36
#define NKT (IN_ / BK)

__global__ __launch_bounds__(256) void gemm_mma_kernel(
    const float* __restrict__ news_vec,
    const float* __restrict__ log_vec,
    const float* __restrict__ W1)
{
    __shared__ uint32_t As[128 * LDT];
    __shared__ uint32_t Ws[128 * LDT];

    int tid  = threadIdx.x;
    int wid  = tid >> 5, lane = tid & 31;
    int gid  = lane >> 2, tig = lane & 3;
    int wm   = wid & 1;
    int wn   = wid >> 1;

    int bx   = blockIdx.x;
    int nh   = bx & 1;
    int tile = bx >> 1;
    int mode, mtile, w_off;
    const float* A;
    if (tile < 32) { mode = 0; mtile = tile;      A = news_vec; w_off = 0; }
    else           { mode = 1; mtile = tile - 32; A = log_vec;  w_off = NEWS_; }
    int n_base = nh * 128;

    int lrow = tid >> 3;
    int lf4  = tid & 7;
    const float* Abase = A  + (size_t)(mtile * 128 + lrow) * IN_ + lf4 * 4;
    const float* Wbase = W1 + (size_t)(n_base + lrow) * W1COLS_ + w_off + lf4 * 4;

    float acc[4][4][4];
    #pragma unroll
    for (int i = 0; i < 4; i++)
        #pragma unroll
        for (int j = 0; j < 4; j++)
            #pragma unroll
            for (int k = 0; k < 4; k++) acc[i][j][k] = 0.f;

    float4 aReg[4], wReg[4];
    #pragma unroll
    for (int p = 0; p < 4; p++) {
        aReg[p] = *(const float4*)(Abase + (size_t)p * 32 * IN_);
        wReg[p] = *(const float4*)(Wbase + (size_t)p * 32 * W1COLS_);
    }

    for (int kt = 0; kt < NKT; kt++) {
        #pragma unroll
        for (int p = 0; p < 4; p++) {
            uint32_t* as = &As[(p * 32 + lrow) * LDT + lf4 * 4];
            as[0] = to_tf32(aReg[p].x); as[1] = to_tf32(aReg[p].y);
            as[2] = to_tf32(aReg[p].z); as[3] = to_tf32(aReg[p].w);
            uint32_t* ws = &Ws[(p * 32 + lrow) * LDT + lf4 * 4];
            ws[0] = to_tf32(wReg[p].x); ws[1] = to_tf32(wReg[p].y);
            ws[2] = to_tf32(wReg[p].z); ws[3] = to_tf32(wReg[p].w);
        }
        __syncthreads();

        if (kt + 1 < NKT) {
            const float* An = Abase + (kt + 1) * BK;
            const float* Wn = Wbase + (kt + 1) * BK;
            #pragma unroll
            for (int p = 0; p < 4; p++) {
                aReg[p] = *(const float4*)(An + (size_t)p * 32 * IN_);
                wReg[p] = *(const float4*)(Wn + (size_t)p * 32 * W1COLS_);
            }
        }

        #pragma unroll
        for (int kk = 0; kk < BK; kk += 8) {
            uint32_t afr[4][4], bfr[4][2];
            #pragma unroll
            for (int mf = 0; mf < 4; mf++) {
                int r0 = (wm * 64 + mf * 16 + gid) * LDT + kk + tig;
                afr[mf][0] = As[r0];
                afr[mf][1] = As[r0 + 8 * LDT];
                afr[mf][2] = As[r0 + 4];
                afr[mf][3] = As[r0 + 8 * LDT + 4];
            }
            #pragma unroll
            for (int nf = 0; nf < 4; nf++) {
                int c0 = (wn * 32 + nf * 8 + gid) * LDT + kk + tig;
                bfr[nf][0] = Ws[c0];
                bfr[nf][1] = Ws[c0 + 4];
            }
            #pragma unroll
            for (int mf = 0; mf < 4; mf++)
                #pragma unroll
                for (int nf = 0; nf < 4; nf++)
                    mma_tf32(acc[mf][nf], afr[mf], bfr[nf]);
        }
        __syncthreads();
    }

    float* outp = (mode == 0) ? g_pn : g_pl;
    #pragma unroll
    for (int mf = 0; mf < 4; mf++) {
        int r0 = mtile * 128 + wm * 64 + mf * 16 + gid;
        int r1 = r0 + 8;
        const float* bias0;
        const float* bias1;
        if (mode == 0) { bias0 = g_cn; bias1 = g_cn; }
        else { bias0 = g_cl + (r0 % HL_) * ATT_; bias1 = g_cl + (r1 % HL_) * ATT_; }
        #pragma unroll
        for (int nf = 0; nf < 4; nf++) {
            int c = n_base + wn * 32 + nf * 8 + 2 * tig;
            float2 v0, v1;
            v0.x = acc[mf][nf][0] + bias0[c];
            v0.y = acc[mf][nf][1] + bias0[c + 1];
            v1.x = acc[mf][nf][2] + bias1[c];
            v1.y = acc[mf][nf][3] + bias1[c + 1];
            *(float2*)(outp + (size_t)r0 * ATT_ + c) = v0;
            *(float2*)(outp + (size_t)r1 * ATT_ + c) = v1;
        }
    }
}

// ---------------------------------------------------------------------------
// Kernel 4a: attn_kernel. Block = (b, quarter of n) -> 16 n's, 1 n per warp.
// smem: pl_s compact (50x256) + act (52). occ target: 2 blocks/SM.
// ---------------------------------------------------------------------------
#define ATTN_SMEM ((50 * 256 + 64) * 4)
__global__ __launch_bounds__(512, 2) void attn_kernel(
    const float* __restrict__ W2,
    const float* __restrict__ b2)
{
    extern __shared__ float sm[];
    float* pl_s  = sm;                 // 50*256
    int*   act_s = (int*)(sm + 12800); // 52

    int tid  = threadIdx.x;
    int b    = blockIdx.x >> 2;
    int q    = blockIdx.x & 3;
    int warp = tid >> 5, lane = tid & 31;

    int cf   = g_cntflag[b];
    int cnt  = cf & 0xff;
    int unif = cf >> 8;

    if (tid < 52) act_s[tid] = g_act[b * 52 + tid];
    __syncthreads();

    // stage compact pl
    {
        int npl = cnt * 64;
        const float4* plg = (const float4*)(g_pl + (size_t)b * HL_ * ATT_);
        for (int i = tid; i < npl; i += 512) {
            int j = i >> 6, r = i & 63;
            ((float4*)pl_s)[j * 64 + r] = plg[(size_t)act_s[j] * 64 + r];
        }
    }
    float w2r[8];
    #pragma unroll
    for (int k = 0; k < 8; k++) w2r[k] = W2[lane + 32 * k];
    float bias2 = b2[0];
    __syncthreads();

    int n  = q * 16 + warp;
    int bn = b * NN_ + n;

    float pnr[8];
    #pragma unroll
    for (int k = 0; k < 8; k++) pnr[k] = g_pn[(size_t)bn * ATT_ + lane + 32 * k];

    if (!unif) {
        float v0 = -3.0e38f, v1 = -3.0e38f;
        for (int j = 0; j < cnt; j++) {
            const float* plrow = pl_s + j * ATT_;
            float s = 0.f;
            #pragma unroll
            for (int k = 0; k < 8; k++)
                s += tanh_fast(pnr[k] + plrow[lane + 32 * k]) * w2r[k];
            #pragma unroll
            for (int o = 16; o > 0; o >>= 1)
                s += __shfl_xor_sync(0xffffffffu, s, o);
            // s is warp-uniform; deposit into owning lane
            if (j < 32) { if (lane == j)      v0 = s + bias2; }
            else        { if (lane == j - 32) v1 = s + bias2; }
        }
        float mx = fmaxf(v0, v1);
        #pragma unroll
        for (int o = 16; o > 0; o >>= 1)
            mx = fmaxf(mx, __shfl_xor_sync(0xffffffffu, mx, o));
        float e0 = __expf(v0 - mx), e1 = __expf(v1 - mx);
        float smv = e0 + e1;
        #pragma unroll
        for (int o = 16; o > 0; o >>= 1)
            smv += __shfl_xor_sync(0xffffffffu, smv, o);
        float inv = 1.f / smv;
        if (lane < cnt)      g_attn[(size_t)bn * 52 + lane]      = e0 * inv;
        if (lane + 32 < cnt) g_attn[(size_t)bn * 52 + lane + 32] = e1 * inv;
    } else {
        float u = 1.f / HL_;
        if (lane < cnt)      g_attn[(size_t)bn * 52 + lane]      = u;
        if (lane + 32 < cnt) g_attn[(size_t)bn * 52 + lane + 32] = u;
    }
}

// ---------------------------------------------------------------------------
// Kernel 4b: out_kernel. Block = (b, half) -> 32 n's. lf in registers.
// ---------------------------------------------------------------------------
#define OUT_SMEM ((32 * 52 + 64) * 4)
__global__ __launch_bounds__(512, 2) void out_kernel(
    const float* __restrict__ log_vec,
    const float* __restrict__ pos_emb,
    float* __restrict__ out)
{
    extern __shared__ float sm[];
    float* attn_s = sm;                  // 32*52
    int*   act_s  = (int*)(sm + 32 * 52);

    int tid  = threadIdx.x;
    int b    = blockIdx.x >> 1;
    int half = blockIdx.x & 1;

    int cnt = g_cntflag[b] & 0xff;
    if (tid < 52) act_s[tid] = g_act[b * 52 + tid];
    __syncthreads();

    // stage attn rows for our 32 n's
    {
        const float* ag = g_attn + ((size_t)(b * NN_ + half * 32)) * 52;
        for (int i = tid; i < 32 * 52; i += 512) {
            int r = i / 52, j = i % 52;
            attn_s[i] = (j < cnt) ? ag[(size_t)r * 52 + j] : 0.f;
        }
    }

    // lf into registers for this thread's d
    float lf_reg[HL_];
    int d = tid;
    if (d < NEWS_) {
        for (int j = 0; j < cnt; j++) {
            int h = act_s[j];
            lf_reg[j] = (d < IN_)
                ? log_vec[(size_t)(b * HL_ + h) * IN_ + d]
                : pos_emb[(size_t)(1 + h) * POS_ + (d - IN_)];
        }
    }
    __syncthreads();

    if (d < NEWS_) {
        for (int i = 0; i < 32; i++) {
            int bn = b * NN_ + half * 32 + i;
            const float* arow = attn_s + i * 52;
            float acc = 0.f;
            int j = 0;
            for (; j + 4 <= cnt; j += 4) {
                acc += arow[j]     * lf_reg[j];
                acc += arow[j + 1] * lf_reg[j + 1];
                acc += arow[j + 2] * lf_reg[j + 2];
                acc += arow[j + 3] * lf_reg[j + 3];
            }
            for (; j < cnt; j++) acc += arow[j] * lf_reg[j];
            out[(size_t)bn * NEWS_ + d] = acc;
        }
    }
}

// ---------------------------------------------------------------------------
extern "C" void kernel_launch(void* const* d_in, const int* in_sizes, int n_in,
                              void* d_out, int out_size)
{
    const float* log_vec  = (const float*)d_in[0];
    const int*   log_mask = (const int*)  d_in[1];
    const float* news_vec = (const float*)d_in[2];
    const float* pos_emb  = (const float*)d_in[3];
    const float* W1       = (const float*)d_in[4];
    const float* b1       = (const float*)d_in[5];
    const float* W2       = (const float*)d_in[6];
    const float* b2       = (const float*)d_in[7];
    float* out = (float*)d_out;

    const int NF_TOTAL = B_ * NN_ * NEWS_;
    cudaFuncSetAttribute(attn_kernel, cudaFuncAttributeMaxDynamicSharedMemorySize, ATTN_SMEM);
    cudaFuncSetAttribute(out_kernel,  cudaFuncAttributeMaxDynamicSharedMemorySize, OUT_SMEM);

    setup_kernel<<<(NF_TOTAL + 255) / 256, 256>>>(news_vec, pos_emb, out + NF_TOTAL);
    cncl_kernel<<<HL_ + 2, 256>>>(pos_emb, W1, b1, log_mask);
    gemm_mma_kernel<<<114, 256>>>(news_vec, log_vec, W1);
    attn_kernel<<<B_ * 4, 512, ATTN_SMEM>>>(W2, b2);
    out_kernel<<<B_ * 2, 512, OUT_SMEM>>>(log_vec, pos_emb, out);
}